// round 5
// baseline (speedup 1.0000x reference)
#include <cuda_runtime.h>
#include <cuda_bf16.h>
#include <math.h>

#define BATCH    32
#define SRC_LEN  2048
#define DIM      1024
#define TOTAL_ROWS (SRC_LEN * BATCH)     // 65536
#define NWARP    8
#define THREADS  (NWARP * 32)            // 256
#define GRID     (TOTAL_ROWS / NWARP)    // 8192 blocks, 1 row per warp (R1 shape)

// Per-batch retirement counters. atomicInc wraps back to 0 after SRC_LEN
// increments, so every graph replay starts from a clean state.
__device__ unsigned int g_cnt[BATCH];

__global__ void __launch_bounds__(THREADS)
fused_attn_kernel(const float* __restrict__ dec_hidden,
                  const float* __restrict__ enc,
                  const float* __restrict__ W,
                  const float* __restrict__ bias,
                  float* __restrict__ out)
{
    __shared__ float4   s_wenc[DIM / 4];   // 4 KB
    __shared__ float    red[NWARP];
    __shared__ float    s_scalar;
    __shared__ unsigned s_norm_mask;

    const int tid  = threadIdx.x;
    const int lane = tid & 31;
    const int warp = tid >> 5;

    if (tid == 0) s_norm_mask = 0;

    // ---- stage w_enc (W[0,1024:2048]) in shared ----
    const float4* we_g = reinterpret_cast<const float4*>(W + DIM);
    for (int i = tid; i < DIM / 4; i += THREADS)
        s_wenc[i] = we_g[i];
    __syncthreads();

    // ---- score: EXACT R1 shape — one row per warp, 8 independent LDG.128 ----
    const int flat = blockIdx.x * NWARP + warp;      // = s*32 + b
    const int s = flat >> 5;
    const int b = flat & 31;
    const int b_base = (blockIdx.x * NWARP) & 31;    // b of warp 0 (0,8,16,24)

    const float4* row = reinterpret_cast<const float4*>(enc + (size_t)flat * DIM);

    float acc = 0.f;
#pragma unroll
    for (int i = 0; i < 8; ++i) {
        float4 v = __ldcs(&row[lane + i * 32]);      // evict-first stream
        float4 w = s_wenc[lane + i * 32];
        acc += v.x * w.x + v.y * w.y + v.z * w.z + v.w * w.w;
    }
#pragma unroll
    for (int o = 16; o > 0; o >>= 1)
        acc += __shfl_xor_sync(0xFFFFFFFFu, acc, o);

    if (lane == 0)
        out[(size_t)b * SRC_LEN + s] = acc;          // raw score

    // ---- retirement: warp 0 lanes 0..7 bump the 8 batch counters ----
    __threadfence();                                  // release our store
    __syncthreads();
    if (warp == 0 && lane < NWARP) {
        unsigned v = atomicInc(&g_cnt[b_base + lane], SRC_LEN - 1);
        if (v == SRC_LEN - 1)
            atomicOr(&s_norm_mask, 1u << lane);       // we retire batch b_base+lane
    }
    __syncthreads();
    unsigned mask = s_norm_mask;
    if (mask == 0) return;
    __threadfence();                                  // acquire before reading rows

    // ---- epilogue: full softmax(tanh(score + e_dec + bias)) per owned batch ----
    while (mask) {
        const int bit = __ffs(mask) - 1;
        mask &= mask - 1;
        const int bb = b_base + bit;

        // e_dec[bb] = dec_hidden[bb,:] . W[0,0:1024]   (256 thr x float4)
        {
            const float4* dh = reinterpret_cast<const float4*>(dec_hidden + (size_t)bb * DIM);
            const float4* wd = reinterpret_cast<const float4*>(W);
            float4 a = dh[tid];
            float4 w = wd[tid];
            float ed = a.x * w.x + a.y * w.y + a.z * w.z + a.w * w.w;
#pragma unroll
            for (int o = 16; o > 0; o >>= 1)
                ed += __shfl_xor_sync(0xFFFFFFFFu, ed, o);
            if (lane == 0) red[warp] = ed;
        }
        __syncthreads();
        if (tid == 0) {
            float t = 0.f;
#pragma unroll
            for (int i = 0; i < NWARP; ++i) t += red[i];
            s_scalar = t + bias[0];
        }
        __syncthreads();
        const float edec = s_scalar;
        __syncthreads();

        // tanh + exp + sum + normalize (tanh in [-1,1] -> no max pass)
        float* rowp = out + (size_t)bb * SRC_LEN;
        float v[SRC_LEN / THREADS];                  // 8 per thread
        float sum = 0.f;
#pragma unroll
        for (int i = 0; i < SRC_LEN / THREADS; ++i) {
            v[i] = __expf(tanhf(__ldcg(&rowp[tid + i * THREADS]) + edec));
            sum += v[i];
        }
#pragma unroll
        for (int o = 16; o > 0; o >>= 1)
            sum += __shfl_xor_sync(0xFFFFFFFFu, sum, o);
        if (lane == 0) red[warp] = sum;
        __syncthreads();
        if (tid == 0) {
            float t = 0.f;
#pragma unroll
            for (int i = 0; i < NWARP; ++i) t += red[i];
            s_scalar = t;
        }
        __syncthreads();
        const float inv = 1.0f / s_scalar;

#pragma unroll
        for (int i = 0; i < SRC_LEN / THREADS; ++i)
            rowp[tid + i * THREADS] = v[i] * inv;
        __syncthreads();
    }
}

// ---------------------------------------------------------------------------
extern "C" void kernel_launch(void* const* d_in, const int* in_sizes, int n_in,
                              void* d_out, int out_size)
{
    const float* dec_hidden  = (const float*)d_in[0];   // (32, 1024)
    const float* enc_outputs = (const float*)d_in[1];   // (2048, 32, 1024)
    const float* W           = (const float*)d_in[2];   // (1, 2048)
    const float* bias        = (const float*)d_in[3];   // (1,)
    float* out = (float*)d_out;                          // (32, 2048)

    fused_attn_kernel<<<GRID, THREADS>>>(dec_hidden, enc_outputs, W, bias, out);
}

// round 6
// speedup vs baseline: 1.0856x; 1.0856x over previous
#include <cuda_runtime.h>
#include <cuda_bf16.h>
#include <math.h>

#define BATCH    32
#define SRC_LEN  2048
#define DIM      1024
#define NWARP    8
#define THREADS  (NWARP * 32)              // 256
#define GRID     (SRC_LEN * BATCH / NWARP) // 8192
#define BLOCKS_PER_BATCH (SRC_LEN / NWARP) // 256

// Padded retirement counters: one per batch, 128 B apart -> distinct LTS
// slices, parallel atomic drain. atomicInc wraps to 0 after BLOCKS_PER_BATCH
// increments, so every graph replay starts clean.
struct __align__(128) PadCnt { unsigned int v; unsigned int pad[31]; };
__device__ PadCnt g_cnt[BATCH];

__global__ void __launch_bounds__(THREADS)
fused_attn_kernel(const float* __restrict__ dec_hidden,
                  const float* __restrict__ enc,
                  const float* __restrict__ W,
                  const float* __restrict__ bias,
                  float* __restrict__ out)
{
    __shared__ float4 s_wenc[DIM / 4];   // 4 KB
    __shared__ float  red[NWARP];
    __shared__ float  s_scalar;
    __shared__ int    s_last;

    const int tid  = threadIdx.x;
    const int lane = tid & 31;
    const int warp = tid >> 5;

    // Block -> (batch, 8 consecutive s rows); warp owns one s row.
    const int b = blockIdx.x & 31;
    const int s = ((blockIdx.x >> 5) * NWARP) + warp;

    // ---- stage w_enc (W[0,1024:2048]) in shared ----
    const float4* we_g = reinterpret_cast<const float4*>(W + DIM);
    for (int i = tid; i < DIM / 4; i += THREADS)
        s_wenc[i] = we_g[i];
    __syncthreads();

    // ---- score: R1 shape — one row per warp, 8 independent LDG.128 ----
    const float4* row = reinterpret_cast<const float4*>(
        enc + ((size_t)s * BATCH + b) * DIM);

    float acc = 0.f;
#pragma unroll
    for (int i = 0; i < 8; ++i) {
        float4 v = row[lane + i * 32];             // plain LDG (R1-measured best)
        float4 w = s_wenc[lane + i * 32];
        acc += v.x * w.x + v.y * w.y + v.z * w.z + v.w * w.w;
    }
#pragma unroll
    for (int o = 16; o > 0; o >>= 1)
        acc += __shfl_xor_sync(0xFFFFFFFFu, acc, o);

    if (lane == 0)
        out[(size_t)b * SRC_LEN + s] = acc;        // raw score

    // ---- retirement: ONE atomic per block, padded counter ----
    __threadfence();                               // release our raw-score store
    __syncthreads();
    if (tid == 0) {
        unsigned v = atomicInc(&g_cnt[b].v, BLOCKS_PER_BATCH - 1);
        s_last = (v == BLOCKS_PER_BATCH - 1);
    }
    __syncthreads();
    if (!s_last) return;
    __threadfence();                               // acquire before reading row

    // ---- epilogue (32 blocks total, one batch each) ----
    // e_dec[b] = dec_hidden[b,:] . W[0,0:1024]   (256 thr x float4)
    {
        const float4* dh = reinterpret_cast<const float4*>(dec_hidden + (size_t)b * DIM);
        const float4* wd = reinterpret_cast<const float4*>(W);
        float4 a = dh[tid];
        float4 w = wd[tid];
        float ed = a.x * w.x + a.y * w.y + a.z * w.z + a.w * w.w;
#pragma unroll
        for (int o = 16; o > 0; o >>= 1)
            ed += __shfl_xor_sync(0xFFFFFFFFu, ed, o);
        if (lane == 0) red[warp] = ed;
    }
    __syncthreads();
    if (tid == 0) {
        float t = 0.f;
#pragma unroll
        for (int i = 0; i < NWARP; ++i) t += red[i];
        s_scalar = t + bias[0];
    }
    __syncthreads();
    const float edec = s_scalar;
    __syncthreads();

    // tanh + exp + sum + normalize (tanh in [-1,1] -> no max pass needed)
    float* rowp = out + (size_t)b * SRC_LEN;
    float v[SRC_LEN / THREADS];                    // 8 per thread
    float sum = 0.f;
#pragma unroll
    for (int i = 0; i < SRC_LEN / THREADS; ++i) {
        v[i] = __expf(tanhf(__ldcg(&rowp[tid + i * THREADS]) + edec));
        sum += v[i];
    }
#pragma unroll
    for (int o = 16; o > 0; o >>= 1)
        sum += __shfl_xor_sync(0xFFFFFFFFu, sum, o);
    if (lane == 0) red[warp] = sum;
    __syncthreads();
    if (tid == 0) {
        float t = 0.f;
#pragma unroll
        for (int i = 0; i < NWARP; ++i) t += red[i];
        s_scalar = t;
    }
    __syncthreads();
    const float inv = 1.0f / s_scalar;

#pragma unroll
    for (int i = 0; i < SRC_LEN / THREADS; ++i)
        rowp[tid + i * THREADS] = v[i] * inv;
}

// ---------------------------------------------------------------------------
extern "C" void kernel_launch(void* const* d_in, const int* in_sizes, int n_in,
                              void* d_out, int out_size)
{
    const float* dec_hidden  = (const float*)d_in[0];   // (32, 1024)
    const float* enc_outputs = (const float*)d_in[1];   // (2048, 32, 1024)
    const float* W           = (const float*)d_in[2];   // (1, 2048)
    const float* bias        = (const float*)d_in[3];   // (1,)
    float* out = (float*)d_out;                          // (32, 2048)

    fused_attn_kernel<<<GRID, THREADS>>>(dec_hidden, enc_outputs, W, bias, out);
}

// round 7
// speedup vs baseline: 1.2389x; 1.1413x over previous
#include <cuda_runtime.h>
#include <cuda_bf16.h>
#include <math.h>

#define BATCH    32
#define SRC_LEN  2048
#define DIM      1024
#define TOTAL_ROWS (SRC_LEN * BATCH)        // 65536
#define WARPS_PER_BLOCK 8
#define BLOCK_THREADS   (WARPS_PER_BLOCK * 32)

// ---------------------------------------------------------------------------
// Kernel A (score): out[b, s] = enc_outputs[s,b,:] . w_enc       (RAW score)
// EXACT R1 shape: flat grid, one row per warp, 8 independent LDG.128/lane.
// ---------------------------------------------------------------------------
__global__ void __launch_bounds__(BLOCK_THREADS)
score_kernel(const float* __restrict__ enc_outputs,
             const float* __restrict__ W,
             float* __restrict__ out)
{
    __shared__ float4 s_wenc[DIM / 4];   // 4 KB

    const float4* we_g = reinterpret_cast<const float4*>(W + DIM);
    for (int i = threadIdx.x; i < DIM / 4; i += BLOCK_THREADS)
        s_wenc[i] = we_g[i];
    __syncthreads();

    const int warp = threadIdx.x >> 5;
    const int lane = threadIdx.x & 31;
    const int flat = blockIdx.x * WARPS_PER_BLOCK + warp;   // = s*32 + b
    const int s = flat >> 5;
    const int b = flat & 31;

    const float4* row = reinterpret_cast<const float4*>(
        enc_outputs + (size_t)flat * DIM);

    float acc = 0.f;
#pragma unroll
    for (int i = 0; i < 8; ++i) {
        float4 v = row[lane + i * 32];
        float4 w = s_wenc[lane + i * 32];
        acc += v.x * w.x + v.y * w.y + v.z * w.z + v.w * w.w;
    }
#pragma unroll
    for (int o = 16; o > 0; o >>= 1)
        acc += __shfl_xor_sync(0xFFFFFFFFu, acc, o);

    if (lane == 0)
        out[(size_t)b * SRC_LEN + s] = acc;   // raw score
}

// ---------------------------------------------------------------------------
// Kernel B: per-batch  e_dec + bias + tanh + exp + sum + normalize, in place.
// tanh output in [-1,1] -> exp cannot overflow -> no max pass.
// 32 blocks x 1024 threads; 2 row values per thread.
// ---------------------------------------------------------------------------
#define SM_THREADS 1024
#define SM_WARPS   (SM_THREADS / 32)        // 32
#define SM_VPT     (SRC_LEN / SM_THREADS)   // 2

__global__ void __launch_bounds__(SM_THREADS)
softmax_kernel(const float* __restrict__ dec_hidden,
               const float* __restrict__ W,
               const float* __restrict__ bias,
               float* __restrict__ out)
{
    __shared__ float red[SM_WARPS];

    const int b    = blockIdx.x;
    const int tid  = threadIdx.x;
    const int lane = tid & 31;
    const int warp = tid >> 5;

    float* row = out + (size_t)b * SRC_LEN;

    // Issue row loads early (independent of e_dec): one float2 per thread
    float2 v = reinterpret_cast<const float2*>(row)[tid];

    // ---- e_dec[b]: 1024 threads x 1 float ----
    float ed = dec_hidden[(size_t)b * DIM + tid] * W[tid];
#pragma unroll
    for (int o = 16; o > 0; o >>= 1)
        ed += __shfl_xor_sync(0xFFFFFFFFu, ed, o);
    if (lane == 0) red[warp] = ed;
    __syncthreads();
    if (warp == 0) {
        float t = red[lane];
#pragma unroll
        for (int o = 16; o > 0; o >>= 1)
            t += __shfl_xor_sync(0xFFFFFFFFu, t, o);
        if (lane == 0) red[0] = t;
    }
    __syncthreads();
    const float edec_b = red[0] + bias[0];
    __syncthreads();

    // ---- tanh + exp + partial sum ----
    v.x = __expf(tanhf(v.x + edec_b));
    v.y = __expf(tanhf(v.y + edec_b));
    float sum = v.x + v.y;
#pragma unroll
    for (int o = 16; o > 0; o >>= 1)
        sum += __shfl_xor_sync(0xFFFFFFFFu, sum, o);
    if (lane == 0) red[warp] = sum;
    __syncthreads();
    if (warp == 0) {
        float t = red[lane];
#pragma unroll
        for (int o = 16; o > 0; o >>= 1)
            t += __shfl_xor_sync(0xFFFFFFFFu, t, o);
        if (lane == 0) red[0] = t;
    }
    __syncthreads();
    const float inv = 1.0f / red[0];

    v.x *= inv;
    v.y *= inv;
    reinterpret_cast<float2*>(row)[tid] = v;
}

// ---------------------------------------------------------------------------
extern "C" void kernel_launch(void* const* d_in, const int* in_sizes, int n_in,
                              void* d_out, int out_size)
{
    const float* dec_hidden  = (const float*)d_in[0];   // (32, 1024)
    const float* enc_outputs = (const float*)d_in[1];   // (2048, 32, 1024)
    const float* W           = (const float*)d_in[2];   // (1, 2048)
    const float* bias        = (const float*)d_in[3];   // (1,)
    float* out = (float*)d_out;                          // (32, 2048)

    score_kernel<<<TOTAL_ROWS / WARPS_PER_BLOCK, BLOCK_THREADS>>>(enc_outputs, W, out);
    softmax_kernel<<<BATCH, SM_THREADS>>>(dec_hidden, W, bias, out);
}